// round 14
// baseline (speedup 1.0000x reference)
#include <cuda_runtime.h>
#include <cuda_bf16.h>
#include <math.h>
#include <stdint.h>

#define NCELL 8192
#define NINP  2000
#define KPAD  2048
#define HDIM  128
#define NOUTD 32
#define BN_EPS 1e-3f

#if defined(__CUDA_ARCH_FEAT_SM103_ALL) || defined(__CUDA_ARCH_FEAT_SM100_ALL) || \
    defined(__CUDA_ARCH_FEAT_SM110_ALL) || defined(__CUDA_ARCH_FEAT_SM101_ALL)
#define TC_ENABLED 1
#else
#define TC_ENABLED 0
#endif

// ---------------------------------------------------------------------------
// Scratch
// ---------------------------------------------------------------------------
__device__ __align__(256) float g_bufA[NCELL * HDIM];
__device__ __align__(256) float g_bufB[NCELL * HDIM];
__device__ __align__(256) float g_qkv [NCELL * 3 * HDIM];
__device__ __align__(256) float g_kagg[NCELL * HDIM];
__device__ __align__(256) float g_stats[768];
__device__ __align__(256) unsigned long long g_rowstats[NCELL];

__device__ __align__(256) __nv_bfloat16 g_q_hi [NCELL * HDIM];
__device__ __align__(256) __nv_bfloat16 g_q_lo [NCELL * HDIM];
__device__ __align__(256) __nv_bfloat16 g_ka_hi[NCELL * HDIM];
__device__ __align__(256) __nv_bfloat16 g_ka_lo[NCELL * HDIM];
__device__ __align__(256) __nv_bfloat16 g_kT_hi[HDIM * NCELL];
__device__ __align__(256) __nv_bfloat16 g_kT_lo[HDIM * NCELL];
__device__ __align__(256) __nv_bfloat16 g_vT_hi[HDIM * NCELL];
__device__ __align__(256) __nv_bfloat16 g_vT_lo[HDIM * NCELL];
__device__ __align__(256) __nv_bfloat16 g_wT_hi[HDIM * KPAD];
__device__ __align__(256) __nv_bfloat16 g_wT_lo[HDIM * KPAD];

// ---------------------------------------------------------------------------
// PTX helpers
// ---------------------------------------------------------------------------
__device__ __forceinline__ uint32_t cvta_smem(const void *p) {
    uint32_t a;
    asm("{ .reg .u64 t; cvta.to.shared.u64 t, %1; cvt.u32.u64 %0, t; }"
        : "=r"(a) : "l"(p));
    return a;
}
__device__ __forceinline__ uint32_t elect_one() {
    uint32_t p;
    asm volatile("{ .reg .pred p; elect.sync _|p, 0xFFFFFFFF; selp.b32 %0, 1, 0, p; }"
                 : "=r"(p));
    return p;
}
__device__ __forceinline__ void mbar_init(uint32_t mbar, uint32_t cnt) {
    asm volatile("mbarrier.init.shared.b64 [%0], %1;"
                 :: "r"(mbar), "r"(cnt) : "memory");
}
__device__ __forceinline__ void mbar_wait(uint32_t mbar, uint32_t parity) {
    asm volatile(
        "{\n\t.reg .pred P;\n"
        "LW_%=:\n\t"
        "mbarrier.try_wait.parity.acquire.cta.shared::cta.b64 P, [%0], %1, 0x989680;\n\t"
        "@P bra LD_%=;\n\t"
        "bra LW_%=;\n"
        "LD_%=:\n\t}"
        :: "r"(mbar), "r"(parity) : "memory");
}
__device__ __forceinline__ void fence_async_smem() {
    asm volatile("fence.proxy.async.shared::cta;" ::: "memory");
}
__device__ __forceinline__ void cpa16(uint32_t dst, const void *src) {
    asm volatile("cp.async.cg.shared.global [%0], [%1], 16;"
                 :: "r"(dst), "l"(src) : "memory");
}
__device__ __forceinline__ void cpa_commit() {
    asm volatile("cp.async.commit_group;" ::: "memory");
}
template <int N>
__device__ __forceinline__ void cpa_wait() {
    asm volatile("cp.async.wait_group %0;" :: "n"(N) : "memory");
}
__device__ __forceinline__ void red4(float *p, float a, float b, float c, float d) {
    asm volatile("red.global.add.v4.f32 [%0], {%1, %2, %3, %4};"
                 :: "l"(p), "f"(a), "f"(b), "f"(c), "f"(d) : "memory");
}

// ---- tcgen05 ----
__device__ __forceinline__ void tc_alloc(uint32_t smem_dst, uint32_t ncols) {
    asm volatile("tcgen05.alloc.cta_group::1.sync.aligned.shared::cta.b32 [%0], %1;"
                 :: "r"(smem_dst), "r"(ncols) : "memory");
}
__device__ __forceinline__ void tc_dealloc(uint32_t tmem, uint32_t ncols) {
    asm volatile("tcgen05.dealloc.cta_group::1.sync.aligned.b32 %0, %1;"
                 :: "r"(tmem), "r"(ncols));
}
__device__ __forceinline__ void tc_relinquish() {
    asm volatile("tcgen05.relinquish_alloc_permit.cta_group::1.sync.aligned;");
}
__device__ __forceinline__ void tc_commit(uint32_t mbar) {
    asm volatile("tcgen05.commit.cta_group::1.mbarrier::arrive::one.shared::cluster.b64 [%0];"
                 :: "r"(mbar) : "memory");
}
__device__ __forceinline__ void tc_fence_after() {
    asm volatile("tcgen05.fence::after_thread_sync;" ::: "memory");
}
__device__ __forceinline__ void tc_wait_ld() {
    asm volatile("tcgen05.wait::ld.sync.aligned;" ::: "memory");
}
__device__ __forceinline__ void ldtm32(uint32_t *r, uint32_t addr) {
    asm volatile(
        "tcgen05.ld.sync.aligned.32x32b.x32.b32 "
        "{%0, %1, %2, %3, %4, %5, %6, %7, "
        " %8, %9, %10, %11, %12, %13, %14, %15, "
        " %16, %17, %18, %19, %20, %21, %22, %23, "
        " %24, %25, %26, %27, %28, %29, %30, %31}, [%32];"
        : "=r"(r[0]),  "=r"(r[1]),  "=r"(r[2]),  "=r"(r[3]),
          "=r"(r[4]),  "=r"(r[5]),  "=r"(r[6]),  "=r"(r[7]),
          "=r"(r[8]),  "=r"(r[9]),  "=r"(r[10]), "=r"(r[11]),
          "=r"(r[12]), "=r"(r[13]), "=r"(r[14]), "=r"(r[15]),
          "=r"(r[16]), "=r"(r[17]), "=r"(r[18]), "=r"(r[19]),
          "=r"(r[20]), "=r"(r[21]), "=r"(r[22]), "=r"(r[23]),
          "=r"(r[24]), "=r"(r[25]), "=r"(r[26]), "=r"(r[27]),
          "=r"(r[28]), "=r"(r[29]), "=r"(r[30]), "=r"(r[31])
        : "r"(addr));
}
__device__ __forceinline__ void mma_f16_ss(uint32_t d, uint64_t a_desc,
                                           uint64_t b_desc, uint32_t idesc,
                                           uint32_t en) {
    asm volatile(
        "{\n\t.reg .pred p;\n\t"
        "setp.ne.u32 p, %5, 0;\n\t"
        "tcgen05.mma.cta_group::1.kind::f16 [%0], %1, %2, %3, {%4, %4, %4, %4}, p;\n\t}"
        :: "r"(d), "l"(a_desc), "l"(b_desc), "r"(idesc), "r"(0u), "r"(en)
        : "memory");
}
__device__ __forceinline__ uint64_t make_desc(uint32_t addr) {
    return ((uint64_t)2 << 61) | ((uint64_t)1 << 46) | ((uint64_t)64 << 32) |
           ((uint64_t)1 << 16) | (((uint64_t)(addr >> 4)) & 0x3FFF);
}
__device__ __forceinline__ void fma2(float2 &c, const float2 &a, const float2 &b) {
    unsigned long long       &cc = reinterpret_cast<unsigned long long &>(c);
    const unsigned long long &aa = reinterpret_cast<const unsigned long long &>(a);
    const unsigned long long &bb = reinterpret_cast<const unsigned long long &>(b);
    asm("fma.rn.f32x2 %0, %1, %2, %0;" : "+l"(cc) : "l"(aa), "l"(bb));
}
__device__ __forceinline__ void split1(float v, __nv_bfloat16 &h, __nv_bfloat16 &l) {
    h = __float2bfloat16(v);
    l = __float2bfloat16(v - __bfloat162float(h));
}
__device__ __forceinline__ void split4_fast(float4 v, uint2 &hi, uint2 &lo) {
    uint32_t h01, h23, l01, l23;
    asm("cvt.rn.bf16x2.f32 %0, %1, %2;" : "=r"(h01) : "f"(v.y), "f"(v.x));
    asm("cvt.rn.bf16x2.f32 %0, %1, %2;" : "=r"(h23) : "f"(v.w), "f"(v.z));
    float r0 = v.x - __uint_as_float(h01 << 16);
    float r1 = v.y - __uint_as_float(h01 & 0xFFFF0000u);
    float r2 = v.z - __uint_as_float(h23 << 16);
    float r3 = v.w - __uint_as_float(h23 & 0xFFFF0000u);
    asm("cvt.rn.bf16x2.f32 %0, %1, %2;" : "=r"(l01) : "f"(r1), "f"(r0));
    asm("cvt.rn.bf16x2.f32 %0, %1, %2;" : "=r"(l23) : "f"(r3), "f"(r2));
    hi = make_uint2(h01, h23);
    lo = make_uint2(l01, l23);
}
__device__ __forceinline__ void merge_stats(unsigned long long *addr, float m2, float s2) {
    unsigned long long old = *addr, assumed;
    do {
        assumed = old;
        float2 cur = *(float2 *)&assumed;
        float mn = fmaxf(cur.x, m2);
        float sn = cur.y * __expf(cur.x - mn) + s2 * __expf(m2 - mn);
        float2 nf = make_float2(mn, sn);
        old = atomicCAS(addr, assumed, *(unsigned long long *)&nf);
    } while (old != assumed);
}

static constexpr uint32_t TC_IDESC = 0x8200490u;

__device__ __forceinline__ uint32_t sw32(int r, int ch) {
    uint32_t byte = ((r >> 3) + (ch >> 3) * 16) * 1024 + (r & 7) * 128 + (ch & 7) * 16;
    return byte ^ ((byte >> 3) & 0x70);
}

// ---------------------------------------------------------------------------
// tc_skinny_f32: C += A_f32 @ (Bhi+Blo)^T   (unchanged)
// ---------------------------------------------------------------------------
#define SKF_SMEM (1024 + 2 * 65536)

__global__ void __launch_bounds__(128)
tc_skinny_f32(const float *__restrict__ A, int lda, int Kvalid,
              const __nv_bfloat16 *__restrict__ Bhi,
              const __nv_bfloat16 *__restrict__ Blo, int ldb,
              float *__restrict__ C, int ldc, int kpc, float alpha)
{
#if TC_ENABLED
    extern __shared__ char sm[];
    const uint32_t sb = cvta_smem(sm);
    const int tid = threadIdx.x;
    const int wid = tid >> 5;

    if (wid == 0) tc_alloc(sb, 128);
    if (tid == 64) mbar_init(sb + 8, 1);
    __syncthreads();
    uint32_t tmem;
    asm volatile("ld.shared.b32 %0, [%1];" : "=r"(tmem) : "r"(sb));

    const int m0 = blockIdx.x * 128;
    const int kb0 = blockIdx.z * kpc;
    const int S = kpc >> 6;

    const int aRow = tid >> 4;
    const int aCol = (tid & 15) * 4;
    const float *aBase = A + (size_t)(m0 + aRow) * lda + aCol;
    const size_t aRowStep = (size_t)8 * lda;
    const uint32_t toffA = (uint32_t)(((tid >> 4) * 128 + (tid & 15) * 8) ^ ((tid >> 4) << 4));
    const int bRow = tid >> 3;
    const int bCol = (tid & 7) * 8;
    const uint32_t toffB = (uint32_t)((((tid >> 3) & 7) * 128 + (tid & 7) * 16) ^
                                      ((((tid >> 3) & 7) << 4)));
    const uint32_t bAtom = (uint32_t)(tid >> 6) * 1024;

    float4 regs[16];

    auto ldA = [&](int s) {
        const int kb = kb0 + s * 64;
        const bool ok = (kb + aCol) < Kvalid;
        const float *p = aBase + kb;
#pragma unroll
        for (int i = 0; i < 16; ++i) {
            regs[i] = ok ? *(const float4 *)(p + i * aRowStep)
                         : make_float4(0.f, 0.f, 0.f, 0.f);
        }
    };
    auto ldB = [&](int s) {
        const uint32_t bh = sb + 1024 + (s & 1) * 65536 + 32768;
        const int kb = kb0 + s * 64;
        const __nv_bfloat16 *ph = Bhi + (size_t)bRow * ldb + kb + bCol;
        const __nv_bfloat16 *pl = Blo + (size_t)bRow * ldb + kb + bCol;
        const uint32_t so0 = bAtom + toffB;
#pragma unroll
        for (int i = 0; i < 8; ++i) {
            uint32_t so = so0 + i * 2048;
            cpa16(bh + so,         ph + (size_t)i * 16 * ldb);
            cpa16(bh + 16384 + so, pl + (size_t)i * 16 * ldb);
        }
        cpa_commit();
    };
    auto stA = [&](int s) {
        char *ah = sm + 1024 + (s & 1) * 65536;
        char *al = ah + 16384;
#pragma unroll
        for (int i = 0; i < 16; ++i) {
            uint2 h, l;
            split4_fast(regs[i], h, l);
            uint32_t sz = toffA + i * 1024;
            *(uint2 *)(ah + sz) = h;
            *(uint2 *)(al + sz) = l;
        }
    };

    ldB(0);
    ldA(0);
    uint32_t ph = 0;
    for (int s = 0; s < S; ++s) {
        cpa_wait<0>();
        stA(s);
        __syncthreads();
        fence_async_smem();
        if (wid == 0 && elect_one()) {
            const uint32_t base = sb + 1024 + (s & 1) * 65536;
            uint64_t dah = make_desc(base);
            uint64_t dal = make_desc(base + 16384);
            uint64_t dbh = make_desc(base + 32768);
            uint64_t dbl = make_desc(base + 49152);
#pragma unroll
            for (int k = 0; k < 4; ++k) {
                uint64_t off = (uint64_t)(k * 2);
                mma_f16_ss(tmem, dah + off, dbh + off, TC_IDESC, (s > 0) || (k > 0));
                mma_f16_ss(tmem, dah + off, dbl + off, TC_IDESC, 1u);
                mma_f16_ss(tmem, dal + off, dbh + off, TC_IDESC, 1u);
            }
            tc_commit(sb + 8);
        }
        if (s + 1 < S) { ldB(s + 1); ldA(s + 1); }
        mbar_wait(sb + 8, ph);
        ph ^= 1;
        __syncthreads();
    }

    tc_fence_after();
#pragma unroll
    for (int part = 0; part < 4; ++part) {
        uint32_t d[32];
        ldtm32(d, tmem + part * 32);
        tc_wait_ld();
        float *cp = C + (size_t)(m0 + tid) * ldc + part * 32;
#pragma unroll
        for (int j = 0; j < 8; ++j)
            red4(cp + j * 4,
                 __uint_as_float(d[j * 4 + 0]) * alpha,
                 __uint_as_float(d[j * 4 + 1]) * alpha,
                 __uint_as_float(d[j * 4 + 2]) * alpha,
                 __uint_as_float(d[j * 4 + 3]) * alpha);
    }
    __syncthreads();
    if (wid == 0) {
        tc_relinquish();
        tc_dealloc(tmem, 128);
    }
#endif
}

// ---------------------------------------------------------------------------
// tc_wide_stats: logits GEMM, row (max, sumexp) stats ONLY (unchanged)
// ---------------------------------------------------------------------------
#define WIDE_SMEM (1024 + 65536 + 131072)

__global__ void __launch_bounds__(128)
tc_wide_stats(const __nv_bfloat16 *__restrict__ Ahi, const __nv_bfloat16 *__restrict__ Alo,
              const __nv_bfloat16 *__restrict__ Bhi, const __nv_bfloat16 *__restrict__ Blo,
              float alpha, unsigned long long *__restrict__ rowstats)
{
#if TC_ENABLED
    extern __shared__ char sm[];
    const uint32_t sb = cvta_smem(sm);
    const int tid = threadIdx.x;
    const int wid = tid >> 5;

    if (wid == 0) tc_alloc(sb, 512);
    if (tid == 64) mbar_init(sb + 8, 1);
    __syncthreads();
    uint32_t tmem;
    asm volatile("ld.shared.b32 %0, [%1];" : "=r"(tmem) : "r"(sb));

    const int m0 = blockIdx.x * 128;
    const int ng0 = blockIdx.y * 512;

    const uint32_t A0 = sb + 1024;
    const uint32_t A1 = A0 + 32768;

    auto load_B = [&](int n) {
        const uint32_t base = sb + 1024 + 65536 + (n & 1) * 65536;
        const int r0 = ng0 + n * 128;
#pragma unroll
        for (int i = tid; i < 2048; i += 128) {
            int r = i >> 4, ch = i & 15;
            uint32_t so = sw32(r, ch);
            cpa16(base + so,         Bhi + (size_t)(r0 + r) * HDIM + ch * 8);
            cpa16(base + 32768 + so, Blo + (size_t)(r0 + r) * HDIM + ch * 8);
        }
        cpa_commit();
    };

#pragma unroll
    for (int i = tid; i < 2048; i += 128) {
        int r = i >> 4, ch = i & 15;
        uint32_t so = sw32(r, ch);
        cpa16(A0 + so, Ahi + (size_t)(m0 + r) * HDIM + ch * 8);
        cpa16(A1 + so, Alo + (size_t)(m0 + r) * HDIM + ch * 8);
    }
    {
        const uint32_t base = sb + 1024 + 65536;
#pragma unroll
        for (int i = tid; i < 2048; i += 128) {
            int r = i >> 4, ch = i & 15;
            uint32_t so = sw32(r, ch);
            cpa16(base + so,         Bhi + (size_t)(ng0 + r) * HDIM + ch * 8);
            cpa16(base + 32768 + so, Blo + (size_t)(ng0 + r) * HDIM + ch * 8);
        }
    }
    cpa_commit();

    uint32_t ph = 0;
    for (int n = 0; n < 4; ++n) {
        if (n + 1 < 4) { load_B(n + 1); cpa_wait<1>(); }
        else           { cpa_wait<0>(); }
        __syncthreads();
        fence_async_smem();
        if (wid == 0 && elect_one()) {
            const uint32_t bbase = sb + 1024 + 65536 + (n & 1) * 65536;
            uint64_t dah = make_desc(A0);
            uint64_t dal = make_desc(A1);
            uint64_t dbh = make_desc(bbase);
            uint64_t dbl = make_desc(bbase + 32768);
            const uint32_t acc = tmem + n * 128;
#pragma unroll
            for (int k = 0; k < 8; ++k) {
                uint64_t off = (uint64_t)((k & 3) * 2 + (k >> 2) * 1024);
                mma_f16_ss(acc, dah + off, dbh + off, TC_IDESC, k > 0);
                mma_f16_ss(acc, dah + off, dbl + off, TC_IDESC, 1u);
                mma_f16_ss(acc, dal + off, dbh + off, TC_IDESC, 1u);
            }
            tc_commit(sb + 8);
        }
        mbar_wait(sb + 8, ph);
        ph ^= 1;
        __syncthreads();
    }

    tc_fence_after();
    float mloc = -1e30f, sloc = 0.f;
    for (int n = 0; n < 4; ++n) {
#pragma unroll
        for (int part = 0; part < 4; ++part) {
            uint32_t d[32];
            ldtm32(d, tmem + n * 128 + part * 32);
            tc_wait_ld();
            float mb = -1e30f;
            float v[32];
#pragma unroll
            for (int c = 0; c < 32; ++c) {
                v[c] = __uint_as_float(d[c]) * alpha;
                mb = fmaxf(mb, v[c]);
            }
            float sb2 = 0.f;
#pragma unroll
            for (int c = 0; c < 32; ++c) sb2 += __expf(v[c] - mb);
            float mn = fmaxf(mloc, mb);
            sloc = sloc * __expf(mloc - mn) + sb2 * __expf(mb - mn);
            mloc = mn;
        }
    }
    merge_stats(&rowstats[m0 + tid], mloc, sloc);

    __syncthreads();
    if (wid == 0) {
        tc_relinquish();
        tc_dealloc(tmem, 512);
    }
#endif
}

// ---------------------------------------------------------------------------
// tc_attn (pipelined): dual logits accumulators LACC0/LACC1 + split mbarriers.
// MMA1(j+1) is issued between h0 and h1 of iteration j, so its latency hides
// under h1's softmax/convert/MMA2; the wait at the top of j+1 is nearly free.
// K prefetch stays AFTER mbar_wait(MMA1(j)) (R13 race fix preserved).
// TMEM: LACC0 = 0..127, LACC1 = 128..255, VACC = 256..383.
// ---------------------------------------------------------------------------
#define AT_QH 1024
#define AT_QL (AT_QH + 32768)
#define AT_KH (AT_QL + 32768)
#define AT_KL (AT_KH + 32768)
#define AT_VH (AT_KL + 32768)
#define AT_VL (AT_VH + 32768)
#define AT_P  (AT_VL + 32768)
#define AT_PH AT_P
#define AT_PL (AT_P + 16384)
#define AT_SMEM (AT_P + 32768)
#define AT_JB 16

__global__ void __launch_bounds__(128)
tc_attn(const __nv_bfloat16 *__restrict__ Qhi, const __nv_bfloat16 *__restrict__ Qlo,
        const __nv_bfloat16 *__restrict__ KAhi, const __nv_bfloat16 *__restrict__ KAlo,
        const __nv_bfloat16 *__restrict__ VThi, const __nv_bfloat16 *__restrict__ VTlo,
        float *__restrict__ attn, float *__restrict__ av,
        const unsigned long long *__restrict__ rowstats, float alpha)
{
#if TC_ENABLED
    extern __shared__ char sm[];
    const uint32_t sb = cvta_smem(sm);
    const int tid = threadIdx.x;
    const int wid = tid >> 5;

    if (wid == 0) tc_alloc(sb, 512);
    if (tid == 64) { mbar_init(sb + 8, 1); mbar_init(sb + 16, 1); }
    __syncthreads();
    uint32_t tmem;
    asm volatile("ld.shared.b32 %0, [%1];" : "=r"(tmem) : "r"(sb));
    const uint32_t VACC = tmem + 256;

    const int m0 = blockIdx.x * 128;
    const int j0 = blockIdx.z * AT_JB;

    float rmax, rinv;
    {
        unsigned long long u = rowstats[m0 + tid];
        float2 st2 = *(float2 *)&u;
        rmax = st2.x;
        rinv = 1.f / st2.y;
    }
    const uint32_t pbase = (uint32_t)((tid >> 3) * 1024 + (tid & 7) * 128);
    const uint32_t pxor  = (uint32_t)((tid & 7) << 4);

    auto load_K = [&](int jblk) {
        const int jn = jblk * 128;
#pragma unroll
        for (int i = tid; i < 2048; i += 128) {
            int r = i >> 4, ch = i & 15;
            uint32_t so = sw32(r, ch);
            size_t off = (size_t)(jn + r) * HDIM + ch * 8;
            cpa16(sb + AT_KH + so, KAhi + off);
            cpa16(sb + AT_KL + so, KAlo + off);
        }
        cpa_commit();
    };
    auto load_V = [&](int jblk) {
        const int jn = jblk * 128;
#pragma unroll
        for (int i = tid; i < 2048; i += 128) {
            int r = i >> 4, ch = i & 15;
            uint32_t so = sw32(r, ch);
            size_t off = (size_t)r * NCELL + jn + ch * 8;
            cpa16(sb + AT_VH + so, VThi + off);
            cpa16(sb + AT_VL + so, VTlo + off);
        }
        cpa_commit();
    };

    const uint64_t dQH = make_desc(sb + AT_QH);
    const uint64_t dQL = make_desc(sb + AT_QL);
    const uint64_t dKH = make_desc(sb + AT_KH);
    const uint64_t dKL = make_desc(sb + AT_KL);
    const uint64_t dVH = make_desc(sb + AT_VH);
    const uint64_t dVL = make_desc(sb + AT_VL);
    const uint64_t dPH = make_desc(sb + AT_PH);
    const uint64_t dPL = make_desc(sb + AT_PL);
    float *st = (float *)(sm + AT_P);

    auto issue_mma1 = [&](int jblk) {  // logits(jblk) -> LACC(jblk&1)
        const uint32_t acc = tmem + (jblk & 1) * 128;
#pragma unroll
        for (int k = 0; k < 8; ++k) {
            uint64_t off = (uint64_t)((k & 3) * 2 + (k >> 2) * 1024);
            mma_f16_ss(acc, dQH + off, dKH + off, TC_IDESC, k > 0);
            mma_f16_ss(acc, dQH + off, dKL + off, TC_IDESC, 1u);
            mma_f16_ss(acc, dQL + off, dKH + off, TC_IDESC, 1u);
        }
        tc_commit(sb + 8);   // mbar1
    };

    // prologue: Q + K(j0) + V(j0), one group; then issue MMA1(0)
#pragma unroll
    for (int i = tid; i < 2048; i += 128) {
        int r = i >> 4, ch = i & 15;
        uint32_t so = sw32(r, ch);
        size_t off = (size_t)(m0 + r) * HDIM + ch * 8;
        cpa16(sb + AT_QH + so, Qhi + off);
        cpa16(sb + AT_QL + so, Qlo + off);
    }
    {
        const int jc0 = j0 * 128;
#pragma unroll
        for (int i = tid; i < 2048; i += 128) {
            int r = i >> 4, ch = i & 15;
            uint32_t so = sw32(r, ch);
            size_t offK = (size_t)(jc0 + r) * HDIM + ch * 8;
            size_t offV = (size_t)r * NCELL + jc0 + ch * 8;
            cpa16(sb + AT_KH + so, KAhi + offK);
            cpa16(sb + AT_KL + so, KAlo + offK);
            cpa16(sb + AT_VH + so, VThi + offV);
            cpa16(sb + AT_VL + so, VTlo + offV);
        }
    }
    cpa_commit();
    cpa_wait<0>();
    __syncthreads();
    fence_async_smem();
    if (wid == 0 && elect_one()) issue_mma1(j0);

    uint32_t ph1 = 0, ph2 = 0;
    for (int jj = 0; jj < AT_JB; ++jj) {
        const int jblk = j0 + jj;
        const int jc0 = jblk * 128;
        const uint32_t LACC = tmem + (jblk & 1) * 128;

        // wait MMA1(jj)  (hidden behind previous iteration's h1 work)
        mbar_wait(sb + 8, ph1);
        ph1 ^= 1;
        tc_fence_after();

        // K buffer free -> prefetch K(jj+1)
        if (jj + 1 < AT_JB) load_K(jblk + 1);

        // ensure V(jj) arrived (pending: [V(jj)?, K(jj+1)?])
        if (jj > 0) {
            if (jj + 1 < AT_JB) cpa_wait<1>(); else cpa_wait<0>();
        }
        __syncthreads();

        // two halves of 64 cols each
#pragma unroll
        for (int h = 0; h < 2; ++h) {
            float v[64];
#pragma unroll
            for (int q = 0; q < 2; ++q) {
                uint32_t d[32];
                ldtm32(d, LACC + h * 64 + q * 32);
                tc_wait_ld();
#pragma unroll
                for (int c = 0; c < 32; ++c) {
                    float x = __uint_as_float(d[c]) * alpha;
                    v[q * 32 + c] = __expf(x - rmax) * rinv;
                }
                __syncthreads();
#pragma unroll
                for (int c = 0; c < 32; ++c) st[tid * 33 + c] = v[q * 32 + c];
                __syncthreads();
                const int col0 = jc0 + h * 64 + q * 32;
#pragma unroll
                for (int i = 0; i < 32; ++i) {
                    int idx = i * 128 + tid;
                    int rr = idx >> 5, cc = idx & 31;
                    attn[(size_t)(m0 + rr) * NCELL + col0 + cc] = st[rr * 33 + cc];
                }
            }
            __syncthreads();
#pragma unroll
            for (int ch = 0; ch < 8; ++ch) {
                float4 a = make_float4(v[ch * 8 + 0], v[ch * 8 + 1],
                                       v[ch * 8 + 2], v[ch * 8 + 3]);
                float4 b = make_float4(v[ch * 8 + 4], v[ch * 8 + 5],
                                       v[ch * 8 + 6], v[ch * 8 + 7]);
                uint2 h0, l0, h1, l1;
                split4_fast(a, h0, l0);
                split4_fast(b, h1, l1);
                uint32_t addr = pbase + ((uint32_t)(ch * 16) ^ pxor);
                *(uint4 *)(sm + AT_PH + addr) = make_uint4(h0.x, h0.y, h1.x, h1.y);
                *(uint4 *)(sm + AT_PL + addr) = make_uint4(l0.x, l0.y, l1.x, l1.y);
            }
            __syncthreads();
            fence_async_smem();
            // MMA2(h): av += P @ V^T  -> mbar2
            if (wid == 0 && elect_one()) {
#pragma unroll
                for (int k = 0; k < 4; ++k) {
                    uint64_t aoff = (uint64_t)(k * 2);
                    uint64_t boff = (uint64_t)(k * 2 + h * 1024);
                    uint32_t en0 = (jj > 0) || (h > 0) || (k > 0);
                    mma_f16_ss(VACC, dPH + aoff, dVH + boff, TC_IDESC, en0);
                    mma_f16_ss(VACC, dPH + aoff, dVL + boff, TC_IDESC, 1u);
                    mma_f16_ss(VACC, dPL + aoff, dVH + boff, TC_IDESC, 1u);
                }
                tc_commit(sb + 16);   // mbar2
            }
            // after h0: issue MMA1(jj+1) into the other LACC (K(jj+1) has landed)
            if (h == 0 && jj + 1 < AT_JB) {
                cpa_wait<0>();        // K(jj+1) complete (only pending group)
                __syncthreads();
                fence_async_smem();
                if (wid == 0 && elect_one()) issue_mma1(jblk + 1);
            }
            mbar_wait(sb + 16, ph2);  // MMA2(h) done -> P buffer reusable
            ph2 ^= 1;
            __syncthreads();
        }
        tc_fence_after();
        // V buffer free (MMA2 h1 done) -> prefetch V(jj+1)
        if (jj + 1 < AT_JB) load_V(jblk + 1);
    }

    // av epilogue
#pragma unroll
    for (int part = 0; part < 4; ++part) {
        uint32_t d[32];
        ldtm32(d, VACC + part * 32);
        tc_wait_ld();
        float *cp = av + (size_t)(m0 + tid) * HDIM + part * 32;
#pragma unroll
        for (int j = 0; j < 8; ++j)
            red4(cp + j * 4,
                 __uint_as_float(d[j * 4 + 0]),
                 __uint_as_float(d[j * 4 + 1]),
                 __uint_as_float(d[j * 4 + 2]),
                 __uint_as_float(d[j * 4 + 3]));
    }
    __syncthreads();
    if (wid == 0) {
        tc_relinquish();
        tc_dealloc(tmem, 512);
    }
#endif
}

__global__ void init_rowstats(unsigned long long *rs)
{
    int i = blockIdx.x * blockDim.x + threadIdx.x;
    float2 z = make_float2(-1e30f, 0.f);
    rs[i] = *(unsigned long long *)&z;
}

// ---------------------------------------------------------------------------
// fp32 -> bf16 hi/lo split kernels (unchanged)
// ---------------------------------------------------------------------------
__global__ void split_cols(const float *__restrict__ src, int ldsrc, int col0,
                           int cols4, __nv_bfloat16 *__restrict__ hi,
                           __nv_bfloat16 *__restrict__ lo)
{
    int idx = blockIdx.x * blockDim.x + threadIdx.x;
    int r = idx / cols4, c = idx - r * cols4;
    float4 v = *(const float4 *)(src + (size_t)r * ldsrc + col0 + c * 4);
    uint2 h, l;
    split4_fast(v, h, l);
    *(uint2 *)(hi + (size_t)idx * 4) = h;
    *(uint2 *)(lo + (size_t)idx * 4) = l;
}

__global__ void wT_split(const float *__restrict__ W, const int *__restrict__ hid,
                         __nv_bfloat16 *__restrict__ hi, __nv_bfloat16 *__restrict__ lo)
{
    __shared__ float t[32][33];
    int r0 = blockIdx.x * 32;
    int c0 = blockIdx.y * 32;
    int tx = threadIdx.x, ty = threadIdx.y;
    const float *Wh = W + (size_t)hid[0] * NINP * HDIM;
#pragma unroll
    for (int i = 0; i < 4; ++i) {
        int r = r0 + ty + i * 8;
        t[ty + i * 8][tx] = (r < NINP) ? Wh[(size_t)r * HDIM + c0 + tx] : 0.f;
    }
    __syncthreads();
#pragma unroll
    for (int i = 0; i < 4; ++i) {
        int c = ty + i * 8;
        float v = t[tx][c];
        __nv_bfloat16 h, l;
        split1(v, h, l);
        size_t o = (size_t)(c0 + c) * KPAD + r0 + tx;
        hi[o] = h;
        lo[o] = l;
    }
}

__global__ void transpose_split(const float *__restrict__ src, int ldsrc, int col0,
                                __nv_bfloat16 *__restrict__ hi,
                                __nv_bfloat16 *__restrict__ lo)
{
    __shared__ float t[32][33];
    int r0 = blockIdx.x * 32, c0 = blockIdx.y * 32;
    int tx = threadIdx.x, ty = threadIdx.y;
#pragma unroll
    for (int i = 0; i < 4; ++i) {
        int r = ty + i * 8;
        t[r][tx] = src[(size_t)(r0 + r) * ldsrc + col0 + c0 + tx];
    }
    __syncthreads();
#pragma unroll
    for (int i = 0; i < 4; ++i) {
        int c = ty + i * 8;
        float v = t[tx][c];
        __nv_bfloat16 h, l;
        split1(v, h, l);
        size_t o = (size_t)(c0 + c) * NCELL + r0 + tx;
        hi[o] = h;
        lo[o] = l;
    }
}

// ---------------------------------------------------------------------------
// gemm_small v3 (unchanged)
// ---------------------------------------------------------------------------
#define GS_AS   0
#define GS_BS   8448
#define GS_BNS  25344
#define GS_BNB  25472
#define GS_SMEM ((25472 + 128) * 4)

template <bool BNA, bool STATS>
__global__ void __launch_bounds__(256)
gemm_small(const float *__restrict__ A, const float *__restrict__ B,
           float *__restrict__ C, int ldb, int ldc,
           const float *__restrict__ bias,
           const float *__restrict__ statsIn,
           const float *__restrict__ g, const float *__restrict__ be,
           const int *__restrict__ hid, int hstride,
           float *__restrict__ statsOut)
{
    extern __shared__ float smf[];
    float *As  = smf + GS_AS;
    float *Bs  = smf + GS_BS;
    float *bnS = smf + GS_BNS;
    float *bnB = smf + GS_BNB;
    const uint32_t sb = cvta_smem(smf);

    const int tid = threadIdx.x;
    const int tx = tid & 15;
    const int ty = tid >> 4;
    const int m0 = blockIdx.x * 64;
    const int n0 = blockIdx.y * 128;

#pragma unroll
    for (int j = 0; j < 8; ++j) {
        int e = j * 256 + tid;
        int m = e >> 5, c = e & 31;
        cpa16(sb + GS_AS * 4 + (uint32_t)(m * 528 + c * 16),
              A + (size_t)(m0 + m) * HDIM + c * 4);
    }
#pragma unroll
    for (int j = 0; j < 16; ++j) {
        int e = j * 256 + tid;
        int k = e >> 5, c = e & 31;
        cpa16(sb + GS_BS * 4 + (uint32_t)(k * 528 + c * 16),
              B + (size_t)k * ldb + n0 + c * 4);
    }
    cpa_commit();

    if (BNA && tid < 128) {
        float s1 = statsIn[tid], s2 = statsIn[128 + tid];
        float mean = s1 * (1.f / (float)NCELL);
        float var = s2 * (1.f / (float)NCELL) - mean * mean;
        float rstd = rsqrtf(var + BN_EPS);
        int off = hid ? hid[0] * hstride : 0;
        float gg = g[off + tid];
        bnS[tid] = gg * rstd;
        bnB[tid] = be[off + tid] - gg * mean * rstd;
    }
    cpa_wait<0>();
    __syncthreads();

    if (BNA) {
#pragma unroll
        for (int j = 0; j < 32; ++j) {
            int e = j * 256 + tid;
            int m = e >> 7, k = e & 127;
            float v = As[m * 132 + k];
            As[m * 132 + k] = fmaxf(fmaf(v, bnS[k], bnB[k]), 0.f);
        }
        __syncthreads();
    }

    float2 acc[4][4];
#pragma unroll
    for (int i = 0; i < 4; ++i)
#pragma unroll
        for (int j = 0; j < 4; ++j) acc[i][j] = make_float2(0.f, 0.f);

    const float *arow0 = As + (ty * 4 + 0) * 132;
    const float *arow1 = As + (ty * 4 + 1) * 132;
    const float *arow2 = As + (ty * 4 + 2) * 132;
    const float *arow3 = As + (ty * 4 + 3) * 132;

#pragma unroll 16
    for (int kk = 0; kk < HDIM; ++kk) {
        float4 b0 = *(const float4 *)&Bs[kk * 132 + tx * 4];
        float4 b1 = *(const float4 *)&Bs[kk * 132 + 64 + tx * 4];
        float2 bp[4] = {make_float2(b0.x, b0.y), make_float2(b0.z, b0.w),
                        make_float2(b1.x, b1.y), make_float2(b1.z, b1.w)};
        float av[4] = {arow0[kk], arow1[kk], arow2[kk], arow3[kk]};
#pragma unroll
        for (int i = 0; i < 4; ++i) {
            float2 aa = make_float2(av[i], av[i]);
#pragma unroll
            for (int j = 0; j < 4; ++j) fma2(acc[i][j], aa, bp[j]);
        }
    }

    float bad0[4] = {0.f, 0.f, 0.f, 0.f}, bad1[4] = {0.f, 0.f, 0.f, 0.f};
    if (bias != nullptr) {
#pragma unroll
        for (int j = 0; j < 4; ++j) {
            bad0[j] = bias[n0 + tx * 4 + j];
            bad1[j] = bias[n0 + 64 + tx * 4 + j];
        }
    }

    float cs[8], cq[8];
#pragma unroll
    for (int j = 0; j < 8; ++j) { cs[j] = 0.f; cq[j] = 0.f; }

#pragma unroll
    for (int i = 0; i < 4; ++i) {
        int r = m0 + ty * 4 + i;
        float v[8] = {acc[i][0].x, acc[i][0].y, acc[i][1].x, acc[i][1].y,
                      acc[i][2].x, acc[i][2].y, acc[i][3].x, acc[i][3].y};
        float w[8];
#pragma unroll
        for (int j = 0; j < 4; ++j) { w[j] = v[j] + bad0[j]; w[4 + j] = v[4 + j] + bad1[j]; }
        if (STATS) {
#pragma unroll
            for (int j = 0; j < 8; ++j) { cs[j] += w[j]; cq[j] += w[j] * w[j]; }
        }
        float *crow = C + (size_t)r * ldc;
        *(float4 *)(crow + n0 + tx * 4)      = make_float4(w[0], w[1], w[2], w[3]);
        *(float4 *)(crow + n0 + 64 + tx * 4) = make_float4(w[4], w[5], w[6], w[7]);
    }

    if (STATS) {
        __syncthreads();
        float *sred = As;
        if (tid < 128) { sred[tid] = 0.f; sred[128 + tid] = 0.f; }
        __syncthreads();
#pragma unroll
        for (int j = 0; j < 8; ++j) {
            int col = (j < 4) ? (tx * 4 + j) : (64 + tx * 4 + (j - 4));
            atomicAdd(&sred[col], cs[j]);
            atomicAdd(&sred[128 + col], cq[j]);
        }
        __syncthreads();
        if (tid < 128) {
            atomicAdd(statsOut + tid, sred[tid]);
            atomicAdd(statsOut + 128 + tid, sred[128 + tid]);
        }
    }
}

// ---------------------------------------------------------------------------
// BatchNorm stats (enc output only)
// ---------------------------------------------------------------------------
__global__ void bn_stats(const float *__restrict__ h, float *__restrict__ stats)
{
    int col = threadIdx.x;
    int r0 = blockIdx.x * 32;
    float s = 0.f, s2 = 0.f;
#pragma unroll 8
    for (int r = 0; r < 32; ++r) {
        float v = h[(size_t)(r0 + r) * HDIM + col];
        s += v; s2 += v * v;
    }
    atomicAdd(&stats[col], s);
    atomicAdd(&stats[128 + col], s2);
}

// ---------------------------------------------------------------------------
// Variational heads
// ---------------------------------------------------------------------------
__global__ void heads_kernel(const float *__restrict__ o,
                             const float *__restrict__ mW, const float *__restrict__ mb,
                             const float *__restrict__ vW, const float *__restrict__ vb,
                             const float *__restrict__ eps,
                             float *__restrict__ qm, float *__restrict__ qv,
                             float *__restrict__ lat)
{
    extern __shared__ float smh[];
    float *Wm  = smh;
    float *Wv  = smh + 4096;
    float *osm = smh + 8192;
    const int t = threadIdx.x;
    const int r0 = blockIdx.x * 128;

    for (int i = t; i < HDIM * NOUTD; i += 256) { Wm[i] = mW[i]; Wv[i] = vW[i]; }
    for (int i = t; i < 128 * HDIM; i += 256) {
        int r = i >> 7, c = i & 127;
        osm[r * 129 + c] = o[(size_t)(r0 + r) * HDIM + c];
    }
    __syncthreads();

    for (int idx = t; idx < 128 * NOUTD; idx += 256) {
        int r = idx >> 5, c = idx & 31;
        const float *orow = &osm[r * 129];
        float dm = 0.f, dv = 0.f;
#pragma unroll 8
        for (int k = 0; k < HDIM; ++k) {
            float ov = orow[k];
            dm += ov * Wm[k * NOUTD + c];
            dv += ov * Wv[k * NOUTD + c];
        }
        int R = r0 + r;
        float mval = dm + mb[c];
        float vval = __expf(dv + vb[c]);
        qm[R * NOUTD + c]  = mval;
        qv[R * NOUTD + c]  = vval;
        lat[R * NOUTD + c] = mval + sqrtf(vval) * eps[R * NOUTD + c];
    }
}

// ---------------------------------------------------------------------------
// Launch
// ---------------------------------------------------------------------------
extern "C" void kernel_launch(void *const *d_in, const int *in_sizes, int n_in,
                              void *d_out, int out_size)
{
    const float *x       = (const float *)d_in[0];
    const float *spatial = (const float *)d_in[1];
    const float *eps     = (const float *)d_in[2];
    const float *enc_W   = (const float *)d_in[3];
    const float *enc_g   = (const float *)d_in[5];
    const float *enc_be  = (const float *)d_in[6];
    const float *sh_W1   = (const float *)d_in[7];
    const float *sh_g1   = (const float *)d_in[9];
    const float *sh_be1  = (const float *)d_in[10];
    const float *sh_W2   = (const float *)d_in[11];
    const float *sh_g2   = (const float *)d_in[13];
    const float *sh_be2  = (const float *)d_in[14];
    const float *qkv_W   = (const float *)d_in[15];
    const float *qkv_b   = (const float *)d_in[16];
    const float *o_W     = (const float *)d_in[17];
    const float *o_b     = (const float *)d_in[18];
    const float *mean_W  = (const float *)d_in[19];
    const float *mean_b  = (const float *)d_in[20];
    const float *var_W   = (const float *)d_in[21];
    const float *var_b   = (const float *)d_in[22];
    const int   *hid     = (const int *)d_in[23];

    float *out = (float *)d_out;
    float *out_qm   = out;
    float *out_qv   = out + (size_t)NCELL * NOUTD;
    float *out_lat  = out + 2 * (size_t)NCELL * NOUTD;
    float *out_attn = out + 3 * (size_t)NCELL * NOUTD;

    float *bufA, *bufB, *qkv, *kagg, *stats;
    unsigned long long *rowstats;
    __nv_bfloat16 *q_hi, *q_lo, *ka_hi, *ka_lo;
    __nv_bfloat16 *kT_hi, *kT_lo, *vT_hi, *vT_lo, *wT_hi, *wT_lo;
    cudaGetSymbolAddress((void **)&bufA, g_bufA);
    cudaGetSymbolAddress((void **)&bufB, g_bufB);
    cudaGetSymbolAddress((void **)&qkv,  g_qkv);
    cudaGetSymbolAddress((void **)&kagg, g_kagg);
    cudaGetSymbolAddress((void **)&stats, g_stats);
    cudaGetSymbolAddress((void **)&rowstats, g_rowstats);
    cudaGetSymbolAddress((void **)&q_hi, g_q_hi);
    cudaGetSymbolAddress((void **)&q_lo, g_q_lo);
    cudaGetSymbolAddress((void **)&ka_hi, g_ka_hi);
    cudaGetSymbolAddress((void **)&ka_lo, g_ka_lo);
    cudaGetSymbolAddress((void **)&kT_hi, g_kT_hi);
    cudaGetSymbolAddress((void **)&kT_lo, g_kT_lo);
    cudaGetSymbolAddress((void **)&vT_hi, g_vT_hi);
    cudaGetSymbolAddress((void **)&vT_lo, g_vT_lo);
    cudaGetSymbolAddress((void **)&wT_hi, g_wT_hi);
    cudaGetSymbolAddress((void **)&wT_lo, g_wT_lo);

    cudaFuncSetAttribute(tc_skinny_f32, cudaFuncAttributeMaxDynamicSharedMemorySize, SKF_SMEM);
    cudaFuncSetAttribute(tc_wide_stats, cudaFuncAttributeMaxDynamicSharedMemorySize, WIDE_SMEM);
    cudaFuncSetAttribute(tc_attn,       cudaFuncAttributeMaxDynamicSharedMemorySize, AT_SMEM);
    cudaFuncSetAttribute((const void *)gemm_small<true, true>,
                         cudaFuncAttributeMaxDynamicSharedMemorySize, GS_SMEM);
    cudaFuncSetAttribute((const void *)gemm_small<true, false>,
                         cudaFuncAttributeMaxDynamicSharedMemorySize, GS_SMEM);
    cudaFuncSetAttribute((const void *)gemm_small<false, false>,
                         cudaFuncAttributeMaxDynamicSharedMemorySize, GS_SMEM);

    const size_t NH_BYTES = (size_t)NCELL * HDIM * sizeof(float);
    const float SCALE = 0.08838834764831845f;
    float *slot0 = stats, *slot1 = stats + 256, *slot2 = stats + 512;

    cudaMemsetAsync(stats, 0, 768 * sizeof(float));
    init_rowstats<<<32, 256>>>(rowstats);

    // 1. encoder: h = x @ enc_W[hid]
    wT_split<<<dim3(64, 4), dim3(32, 8)>>>(enc_W, hid, wT_hi, wT_lo);
    cudaMemsetAsync(bufA, 0, NH_BYTES);
    tc_skinny_f32<<<dim3(64, 1, 4), 128, SKF_SMEM>>>(
        x, NINP, NINP, wT_hi, wT_lo, KPAD, bufA, HDIM, 512, 1.f);
    bn_stats<<<256, 128>>>(bufA, slot0);

    // 2. sh1 = BN1(bufA) @ W1 ; stats -> slot1
    gemm_small<true, true><<<dim3(128, 1), 256, GS_SMEM>>>(
        bufA, sh_W1, bufB, HDIM, HDIM, nullptr,
        slot0, enc_g, enc_be, hid, HDIM, slot1);

    // 3. sh2 = BN2(bufB) @ W2 ; stats -> slot2
    gemm_small<true, true><<<dim3(128, 1), 256, GS_SMEM>>>(
        bufB, sh_W2, bufA, HDIM, HDIM, nullptr,
        slot1, sh_g1, sh_be1, nullptr, 0, slot2);

    // 4. qkv = BN3(bufA) @ qkv_W + qkv_b
    gemm_small<true, false><<<dim3(128, 3), 256, GS_SMEM>>>(
        bufA, qkv_W, qkv, 3 * HDIM, 3 * HDIM, qkv_b,
        slot2, sh_g2, sh_be2, nullptr, 0, nullptr);

    // 5. small bf16 conversions (q, kT, vT)
    split_cols<<<1024, 256>>>(qkv, 3 * HDIM, 0, HDIM / 4, q_hi, q_lo);
    transpose_split<<<dim3(256, 4), dim3(32, 8)>>>(qkv, 3 * HDIM, HDIM, kT_hi, kT_lo);
    transpose_split<<<dim3(256, 4), dim3(32, 8)>>>(qkv, 3 * HDIM, 2 * HDIM, vT_hi, vT_lo);

    // 6. k_agg = spatial @ k
    cudaMemsetAsync(kagg, 0, NH_BYTES);
    tc_skinny_f32<<<dim3(64, 1, 4), 128, SKF_SMEM>>>(
        spatial, NCELL, NCELL, kT_hi, kT_lo, NCELL, kagg, HDIM, 2048, 1.f);
    split_cols<<<1024, 256>>>(kagg, HDIM, 0, HDIM / 4, ka_hi, ka_lo);

    // 7. pass 1: row softmax stats (no logits store)
    tc_wide_stats<<<dim3(64, 16), 128, WIDE_SMEM>>>(q_hi, q_lo, ka_hi, ka_lo,
                                                    SCALE, rowstats);

    // 8. pass 2: recompute logits, softmax -> attn output, av = attn @ v
    cudaMemsetAsync(bufA, 0, NH_BYTES);
    tc_attn<<<dim3(64, 1, 4), 128, AT_SMEM>>>(
        q_hi, q_lo, ka_hi, ka_lo, vT_hi, vT_lo, out_attn, bufA, rowstats, SCALE);

    // 9. o = av @ o_W + o_b
    gemm_small<false, false><<<dim3(128, 1), 256, GS_SMEM>>>(
        bufA, o_W, bufB, HDIM, HDIM, o_b,
        nullptr, nullptr, nullptr, nullptr, 0, nullptr);

    // 10. variational heads
    const int heads_smem = (4096 + 4096 + 128 * 129) * sizeof(float);
    cudaFuncSetAttribute(heads_kernel, cudaFuncAttributeMaxDynamicSharedMemorySize,
                         heads_smem);
    heads_kernel<<<64, 256, heads_smem>>>(bufB, mean_W, mean_b, var_W, var_b,
                                          eps, out_qm, out_qv, out_lat);
}